// round 2
// baseline (speedup 1.0000x reference)
#include <cuda_runtime.h>

// TwoBranchDH_SFNN fused kernel for GB300 (sm_103a).
// One block per batch element b. 256 threads; each thread owns 2 hidden
// channels (h0=2*tid, h1=h0+1) packed into f32x2 lanes. All three
// recurrences run in registers; x is staged in smem in duplicated-pair
// layout so LDS.128 feeds fma.rn.f32x2 directly.

namespace {

constexpr int B_SZ  = 128;
constexpr int T_SZ  = 2048;
constexpr int H_SZ  = 512;
constexpr int DIN   = 40;
constexpr int KHALF = 20;
constexpr int THREADS = 256;      // H_SZ / 2
constexpr int TS = 64;            // timesteps per smem tile
constexpr int NTILES = T_SZ / TS;

typedef unsigned long long u64;

__device__ __forceinline__ u64 pk(float lo, float hi) {
    u64 r;
    asm("mov.b64 %0, {%1, %2};" : "=l"(r) : "f"(lo), "f"(hi));
    return r;
}

__device__ __forceinline__ float2 unpk(u64 v) {
    float2 r;
    asm("mov.b64 {%0, %1}, %2;" : "=f"(r.x), "=f"(r.y) : "l"(v));
    return r;
}

__device__ __forceinline__ u64 fma2(u64 a, u64 b, u64 c) {
    u64 d;
    asm("fma.rn.f32x2 %0, %1, %2, %3;" : "=l"(d) : "l"(a), "l"(b), "l"(c));
    return d;
}

__device__ __forceinline__ u64 add2(u64 a, u64 b) {
    u64 d;
    asm("add.rn.f32x2 %0, %1, %2;" : "=l"(d) : "l"(a), "l"(b));
    return d;
}

__device__ __forceinline__ u64 mul2(u64 a, u64 b) {
    u64 d;
    asm("mul.rn.f32x2 %0, %1, %2;" : "=l"(d) : "l"(a), "l"(b));
    return d;
}

__device__ __forceinline__ float sigmoid_acc(float v) {
    return 1.0f / (1.0f + expf(-v));
}

__global__ void __launch_bounds__(THREADS, 1)
sfnn_fused_kernel(const float* __restrict__ x,
                  const float* __restrict__ W1,
                  const float* __restrict__ b1,
                  const float* __restrict__ W2,
                  const float* __restrict__ b2,
                  const float* __restrict__ Wo,
                  const float* __restrict__ bo,
                  const float* __restrict__ tau_m,
                  const float* __restrict__ tau_n1,
                  const float* __restrict__ tau_n2,
                  float* __restrict__ out) {
    // duplicated x tile: for each t, 40 (x_k, x_k) pairs = 320 bytes/row
    __shared__ float xs[TS * DIN * 2];   // 20480 B
    __shared__ float red[8 * 8];         // [warp][j]

    const int tid  = threadIdx.x;
    const int lane = tid & 31;
    const int warp = tid >> 5;
    const int b    = blockIdx.x;
    const int h0   = tid * 2;
    const int h1   = h0 + 1;

    // ---- per-thread constants (computed once, packed f32x2) ----
    const float be1a = sigmoid_acc(tau_n1[h0]), be1b = sigmoid_acc(tau_n1[h1]);
    const float be2a = sigmoid_acc(tau_n2[h0]), be2b = sigmoid_acc(tau_n2[h1]);
    const float ala  = sigmoid_acc(tau_m[h0]),  alb  = sigmoid_acc(tau_m[h1]);

    const u64 B1  = pk(be1a, be1b);
    const u64 G1  = pk(1.0f - be1a, 1.0f - be1b);
    const u64 GB1 = pk((1.0f - be1a) * b1[h0], (1.0f - be1b) * b1[h1]);
    const u64 B2  = pk(be2a, be2b);
    const u64 G2  = pk(1.0f - be2a, 1.0f - be2b);
    const u64 GB2 = pk((1.0f - be2a) * b2[h0], (1.0f - be2b) * b2[h1]);
    const u64 AL  = pk(ala, alb);
    const u64 AM  = pk(1.0f - ala, 1.0f - alb);
    const u64 WOp = pk(Wo[h0], Wo[h1]);
    const float bov = bo[0];

    // ---- weights in registers: w[k] = (Wbranch[h0][k'], Wbranch[h1][k']) ----
    u64 w[DIN];
#pragma unroll
    for (int k = 0; k < KHALF; k++)
        w[k] = pk(W1[h0 * KHALF + k], W1[h1 * KHALF + k]);
#pragma unroll
    for (int k = 0; k < KHALF; k++)
        w[KHALF + k] = pk(W2[h0 * KHALF + k], W2[h1 * KHALF + k]);

    // ---- recurrence state (packed zeros) ----
    u64 d1 = 0ull, d2 = 0ull, mem = 0ull;

    const float4* xg = (const float4*)(x + (size_t)b * T_SZ * DIN);
    float* ob = out + (size_t)b * T_SZ;

    for (int tile = 0; tile < NTILES; tile++) {
        // stage x tile with value duplication: (a,b,c,d) -> (a,a,b,b),(c,c,d,d)
        __syncthreads();
        {
            const float4* src = xg + tile * (TS * DIN / 4);
            float4* dst = (float4*)xs;
            for (int j = tid; j < TS * DIN / 4; j += THREADS) {
                float4 v = src[j];
                dst[2 * j]     = make_float4(v.x, v.x, v.y, v.y);
                dst[2 * j + 1] = make_float4(v.z, v.z, v.w, v.w);
            }
        }
        __syncthreads();

        for (int g = 0; g < TS / 8; g++) {
            float ctr[8];
#pragma unroll
            for (int j = 0; j < 8; j++) {
                const int tl = g * 8 + j;
                const ulonglong2* row =
                    (const ulonglong2*)(xs + tl * (DIN * 2));
                u64 a0 = 0ull, a1 = 0ull, a2 = 0ull, a3 = 0ull;
#pragma unroll
                for (int q = 0; q < 10; q++) {      // branch 1 (k = 0..19)
                    ulonglong2 v = row[q];
                    a0 = fma2(w[2 * q],     v.x, a0);
                    a1 = fma2(w[2 * q + 1], v.y, a1);
                }
#pragma unroll
                for (int q = 10; q < 20; q++) {     // branch 2 (k = 20..39)
                    ulonglong2 v = row[q];
                    a2 = fma2(w[2 * q],     v.x, a2);
                    a3 = fma2(w[2 * q + 1], v.y, a3);
                }
                const u64 dot1 = add2(a0, a1);
                const u64 dot2 = add2(a2, a3);

                // d1 = beta1*d1 + (1-beta1)*(dot1 + b1)
                d1 = fma2(B1, d1, fma2(G1, dot1, GB1));
                d2 = fma2(B2, d2, fma2(G2, dot2, GB2));
                // mem = alpha*mem + (1-alpha)*(d1+d2)
                mem = fma2(AL, mem, mul2(AM, add2(d1, d2)));

                const float2 po = unpk(mul2(WOp, mem));
                ctr[j] = po.x + po.y;
            }

            // warp-level butterfly reduce (8 timesteps at once)
#pragma unroll
            for (int j = 0; j < 8; j++) {
#pragma unroll
                for (int off = 16; off; off >>= 1)
                    ctr[j] += __shfl_xor_sync(0xFFFFFFFFu, ctr[j], off);
            }

            __syncthreads();   // red[] safe to overwrite
            if (lane == 0) {
#pragma unroll
                for (int j = 0; j < 8; j++) red[warp * 8 + j] = ctr[j];
            }
            __syncthreads();
            if (tid < 8) {
                float s = 0.0f;
#pragma unroll
                for (int wv = 0; wv < 8; wv++) s += red[wv * 8 + tid];
                const int t = tile * TS + g * 8 + tid;
                ob[t] = 1.0f / (1.0f + __expf(-(s + bov)));
            }
        }
    }
}

}  // namespace

extern "C" void kernel_launch(void* const* d_in, const int* in_sizes, int n_in,
                              void* d_out, int out_size) {
    const float* x      = (const float*)d_in[0];
    const float* W1     = (const float*)d_in[1];
    const float* b1     = (const float*)d_in[2];
    const float* W2     = (const float*)d_in[3];
    const float* b2     = (const float*)d_in[4];
    const float* Wo     = (const float*)d_in[5];
    const float* bo     = (const float*)d_in[6];
    const float* tau_m  = (const float*)d_in[7];
    const float* tau_n1 = (const float*)d_in[8];
    const float* tau_n2 = (const float*)d_in[9];
    float* out = (float*)d_out;

    sfnn_fused_kernel<<<B_SZ, THREADS>>>(x, W1, b1, W2, b2, Wo, bo,
                                         tau_m, tau_n1, tau_n2, out);
}

// round 3
// speedup vs baseline: 1.2884x; 1.2884x over previous
#include <cuda_runtime.h>

// TwoBranchDH_SFNN fused kernel, R3.
// One block per batch element. 256 threads x 2 hidden channels each.
// x tile staged TRANSPOSED in smem (xs[k][t]) so one broadcast LDS.128
// delivers x[k] for 4 consecutive timesteps; GEMM accumulates with
// fma.rn.f32x2 packed over timestep pairs (t0,t1)/(t2,t3). Recurrence
// stays packed over the channel pair as before.

namespace {

constexpr int B_SZ  = 128;
constexpr int T_SZ  = 2048;
constexpr int DIN   = 40;
constexpr int KHALF = 20;
constexpr int THREADS = 256;
constexpr int TS  = 64;            // timesteps per smem tile
constexpr int TSP = 68;            // padded stride (mult of 4, !=0 mod 32)
constexpr int NTILES = T_SZ / TS;

typedef unsigned long long u64;

__device__ __forceinline__ u64 pk(float lo, float hi) {
    u64 r;
    asm("mov.b64 %0, {%1, %2};" : "=l"(r) : "f"(lo), "f"(hi));
    return r;
}

__device__ __forceinline__ float2 unpk(u64 v) {
    float2 r;
    asm("mov.b64 {%0, %1}, %2;" : "=f"(r.x), "=f"(r.y) : "l"(v));
    return r;
}

__device__ __forceinline__ u64 fma2(u64 a, u64 b, u64 c) {
    u64 d;
    asm("fma.rn.f32x2 %0, %1, %2, %3;" : "=l"(d) : "l"(a), "l"(b), "l"(c));
    return d;
}

__device__ __forceinline__ u64 add2(u64 a, u64 b) {
    u64 d;
    asm("add.rn.f32x2 %0, %1, %2;" : "=l"(d) : "l"(a), "l"(b));
    return d;
}

__device__ __forceinline__ u64 mul2(u64 a, u64 b) {
    u64 d;
    asm("mul.rn.f32x2 %0, %1, %2;" : "=l"(d) : "l"(a), "l"(b));
    return d;
}

__device__ __forceinline__ float sigmoid_acc(float v) {
    return 1.0f / (1.0f + expf(-v));
}

__global__ void __launch_bounds__(THREADS, 1)
sfnn_fused_kernel(const float* __restrict__ x,
                  const float* __restrict__ W1,
                  const float* __restrict__ b1,
                  const float* __restrict__ W2,
                  const float* __restrict__ b2,
                  const float* __restrict__ Wo,
                  const float* __restrict__ bo,
                  const float* __restrict__ tau_m,
                  const float* __restrict__ tau_n1,
                  const float* __restrict__ tau_n2,
                  float* __restrict__ out) {
    __shared__ float xs[DIN * TSP];   // transposed tile: xs[k*TSP + t], 10880 B
    __shared__ float red[8 * 8];      // [warp][j]

    const int tid  = threadIdx.x;
    const int lane = tid & 31;
    const int warp = tid >> 5;
    const int b    = blockIdx.x;
    const int h0   = tid * 2;
    const int h1   = h0 + 1;

    // ---- per-thread recurrence constants (channel-pair packed) ----
    const float be1a = sigmoid_acc(tau_n1[h0]), be1b = sigmoid_acc(tau_n1[h1]);
    const float be2a = sigmoid_acc(tau_n2[h0]), be2b = sigmoid_acc(tau_n2[h1]);
    const float ala  = sigmoid_acc(tau_m[h0]),  alb  = sigmoid_acc(tau_m[h1]);

    const u64 B1  = pk(be1a, be1b);
    const u64 G1  = pk(1.0f - be1a, 1.0f - be1b);
    const u64 GB1 = pk((1.0f - be1a) * b1[h0], (1.0f - be1b) * b1[h1]);
    const u64 B2  = pk(be2a, be2b);
    const u64 G2  = pk(1.0f - be2a, 1.0f - be2b);
    const u64 GB2 = pk((1.0f - be2a) * b2[h0], (1.0f - be2b) * b2[h1]);
    const u64 AL  = pk(ala, alb);
    const u64 AM  = pk(1.0f - ala, 1.0f - alb);
    const u64 WOp = pk(Wo[h0], Wo[h1]);
    const float bov = bo[0];

    // ---- duplicated weights in registers: (w,w) per channel per k ----
    u64 w1a[KHALF], w1b[KHALF], w2a[KHALF], w2b[KHALF];
#pragma unroll
    for (int k = 0; k < KHALF; k++) {
        float v;
        v = W1[h0 * KHALF + k]; w1a[k] = pk(v, v);
        v = W1[h1 * KHALF + k]; w1b[k] = pk(v, v);
        v = W2[h0 * KHALF + k]; w2a[k] = pk(v, v);
        v = W2[h1 * KHALF + k]; w2b[k] = pk(v, v);
    }

    // ---- recurrence state (channel-pair packed) ----
    u64 d1 = 0ull, d2 = 0ull, mem = 0ull;

    const float4* xg = (const float4*)(x + (size_t)b * T_SZ * DIN);
    float* ob = out + (size_t)b * T_SZ;

    for (int tile = 0; tile < NTILES; tile++) {
        // ---- stage transposed: global (t-major) -> xs[k][t] ----
        {
            const float4* src = xg + tile * (TS * DIN / 4);
            for (int idx = tid; idx < TS * DIN / 4; idx += THREADS) {
                const int tt = idx / (DIN / 4);
                const int k4 = idx % (DIN / 4);
                float4 v = src[idx];                // coalesced
                xs[(4 * k4 + 0) * TSP + tt] = v.x;
                xs[(4 * k4 + 1) * TSP + tt] = v.y;
                xs[(4 * k4 + 2) * TSP + tt] = v.z;
                xs[(4 * k4 + 3) * TSP + tt] = v.w;
            }
        }
        __syncthreads();

        for (int g = 0; g < TS / 8; g++) {
            float ctr[8];
#pragma unroll
            for (int half = 0; half < 2; half++) {
                const int t0 = g * 8 + half * 4;
                const float* base = xs + t0;

                // GEMM for 4 timesteps: accs packed over t-pairs
                u64 a1A_01 = 0ull, a1A_23 = 0ull;   // branch1, h0
                u64 a1B_01 = 0ull, a1B_23 = 0ull;   // branch1, h1
                u64 a2A_01 = 0ull, a2A_23 = 0ull;   // branch2, h0
                u64 a2B_01 = 0ull, a2B_23 = 0ull;   // branch2, h1
#pragma unroll
                for (int k = 0; k < KHALF; k++) {
                    const ulonglong2 v =
                        *(const ulonglong2*)(base + k * TSP);  // x[k][t0..t3]
                    a1A_01 = fma2(w1a[k], v.x, a1A_01);
                    a1A_23 = fma2(w1a[k], v.y, a1A_23);
                    a1B_01 = fma2(w1b[k], v.x, a1B_01);
                    a1B_23 = fma2(w1b[k], v.y, a1B_23);
                }
#pragma unroll
                for (int k = 0; k < KHALF; k++) {
                    const ulonglong2 v =
                        *(const ulonglong2*)(base + (KHALF + k) * TSP);
                    a2A_01 = fma2(w2a[k], v.x, a2A_01);
                    a2A_23 = fma2(w2a[k], v.y, a2A_23);
                    a2B_01 = fma2(w2b[k], v.x, a2B_01);
                    a2B_23 = fma2(w2b[k], v.y, a2B_23);
                }

                const float2 d1A01 = unpk(a1A_01), d1A23 = unpk(a1A_23);
                const float2 d1B01 = unpk(a1B_01), d1B23 = unpk(a1B_23);
                const float2 d2A01 = unpk(a2A_01), d2A23 = unpk(a2A_23);
                const float2 d2B01 = unpk(a2B_01), d2B23 = unpk(a2B_23);

                const float i1A[4] = {d1A01.x, d1A01.y, d1A23.x, d1A23.y};
                const float i1B[4] = {d1B01.x, d1B01.y, d1B23.x, d1B23.y};
                const float i2A[4] = {d2A01.x, d2A01.y, d2A23.x, d2A23.y};
                const float i2B[4] = {d2B01.x, d2B01.y, d2B23.x, d2B23.y};

#pragma unroll
                for (int j = 0; j < 4; j++) {
                    const u64 dot1 = pk(i1A[j], i1B[j]);
                    const u64 dot2 = pk(i2A[j], i2B[j]);
                    d1 = fma2(B1, d1, fma2(G1, dot1, GB1));
                    d2 = fma2(B2, d2, fma2(G2, dot2, GB2));
                    mem = fma2(AL, mem, mul2(AM, add2(d1, d2)));
                    const float2 po = unpk(mul2(WOp, mem));
                    ctr[half * 4 + j] = po.x + po.y;
                }
            }

            // block reduction over H for 8 timesteps
#pragma unroll
            for (int j = 0; j < 8; j++) {
#pragma unroll
                for (int off = 16; off; off >>= 1)
                    ctr[j] += __shfl_xor_sync(0xFFFFFFFFu, ctr[j], off);
            }

            __syncthreads();
            if (lane == 0) {
#pragma unroll
                for (int j = 0; j < 8; j++) red[warp * 8 + j] = ctr[j];
            }
            __syncthreads();
            if (tid < 8) {
                float s = 0.0f;
#pragma unroll
                for (int wv = 0; wv < 8; wv++) s += red[wv * 8 + tid];
                const int t = tile * TS + g * 8 + tid;
                ob[t] = 1.0f / (1.0f + __expf(-(s + bov)));
            }
        }
    }
}

}  // namespace

extern "C" void kernel_launch(void* const* d_in, const int* in_sizes, int n_in,
                              void* d_out, int out_size) {
    const float* x      = (const float*)d_in[0];
    const float* W1     = (const float*)d_in[1];
    const float* b1     = (const float*)d_in[2];
    const float* W2     = (const float*)d_in[3];
    const float* b2     = (const float*)d_in[4];
    const float* Wo     = (const float*)d_in[5];
    const float* bo     = (const float*)d_in[6];
    const float* tau_m  = (const float*)d_in[7];
    const float* tau_n1 = (const float*)d_in[8];
    const float* tau_n2 = (const float*)d_in[9];
    float* out = (float*)d_out;

    sfnn_fused_kernel<<<B_SZ, THREADS>>>(x, W1, b1, W2, b2, Wo, bo,
                                         tau_m, tau_n1, tau_n2, out);
}

// round 6
// speedup vs baseline: 1.8685x; 1.4503x over previous
#include <cuda_runtime.h>
#include <cuda_fp16.h>
#include <cstdint>

// TwoBranchDH_SFNN, R5: warp-level mma.sync (HMMA fallback) GEMM + fused
// register recurrence. grid=128 (block per batch), 512 threads (16 warps).
// M=16 timesteps, N=channels, K=20(pad32), fp16 inputs / f32 accum.
// W fragments permanent in registers; x staged fp16 in smem via ldmatrix;
// dots transposed through a bank-engineered smem bounce; (d1,d2) recurrence
// packed in fma.rn.f32x2; output reduced via smem y-buffer.

namespace {

constexpr int B_SZ  = 128;
constexpr int T_SZ  = 2048;
constexpr int DIN   = 40;
constexpr int KHALF = 20;
constexpr int THREADS = 512;
constexpr int ST      = 16;             // timesteps per stage
constexpr int NSTAGES = T_SZ / ST;      // 128

// smem geometry (32-bit words)
constexpr int TCW  = 513 * 4;           // words per tc-slab (padded vs 512*4)
constexpr int BRW  = 4 * TCW;           // per-branch dot words
constexpr int DOTW = 2 * BRW;           // both branches
constexpr int YW   = 520;               // y row stride (words)
constexpr int YTOT = 16 * YW;
constexpr int XW   = 16 * 64;           // halves per x buffer
constexpr int SMEM_BYTES = (DOTW + YTOT) * 4 + 2 * XW * 2;   // 103040 B

typedef unsigned long long u64;
typedef uint32_t u32;

__device__ __forceinline__ u32 smem_u32(const void* p) {
    u32 a;
    asm("{ .reg .u64 t; cvta.to.shared.u64 t, %1; cvt.u32.u64 %0, t; }"
        : "=r"(a) : "l"(p));
    return a;
}
__device__ __forceinline__ u64 pkf(float lo, float hi) {
    u64 r; asm("mov.b64 %0, {%1, %2};" : "=l"(r) : "f"(lo), "f"(hi)); return r;
}
__device__ __forceinline__ float2 unpk(u64 v) {
    float2 r; asm("mov.b64 {%0, %1}, %2;" : "=f"(r.x), "=f"(r.y) : "l"(v)); return r;
}
__device__ __forceinline__ u64 fma2(u64 a, u64 b, u64 c) {
    u64 d; asm("fma.rn.f32x2 %0, %1, %2, %3;" : "=l"(d) : "l"(a), "l"(b), "l"(c)); return d;
}

__device__ __forceinline__ void ldmat4(u32* r, u32 addr) {
    asm volatile("ldmatrix.sync.aligned.m8n8.x4.shared.b16 {%0,%1,%2,%3}, [%4];"
                 : "=r"(r[0]), "=r"(r[1]), "=r"(r[2]), "=r"(r[3]) : "r"(addr));
}
__device__ __forceinline__ void mma16816(float& d0, float& d1, float& d2, float& d3,
                                         const u32* a, u32 b0, u32 b1) {
    asm volatile("mma.sync.aligned.m16n8k16.row.col.f32.f16.f16.f32 "
                 "{%0,%1,%2,%3}, {%4,%5,%6,%7}, {%8,%9}, {%0,%1,%2,%3};"
                 : "+f"(d0), "+f"(d1), "+f"(d2), "+f"(d3)
                 : "r"(a[0]), "r"(a[1]), "r"(a[2]), "r"(a[3]), "r"(b0), "r"(b1));
}
__device__ __forceinline__ float sigf(float v) { return 1.0f / (1.0f + expf(-v)); }
__device__ __forceinline__ u32 packh(float a, float b) {
    __half2 h = __floats2half2_rn(a, b);
    return *reinterpret_cast<u32*>(&h);
}

__global__ void __launch_bounds__(THREADS, 1)
sfnn_mma_kernel(const float* __restrict__ x,
                const float* __restrict__ W1, const float* __restrict__ b1,
                const float* __restrict__ W2, const float* __restrict__ b2,
                const float* __restrict__ Wo, const float* __restrict__ bo,
                const float* __restrict__ tau_m, const float* __restrict__ tau_n1,
                const float* __restrict__ tau_n2, float* __restrict__ out) {
    extern __shared__ __align__(16) float sm[];
    float* dotsm = sm;                          // DOTW words
    float* ysm   = sm + DOTW;                   // YTOT words
    __half* xsm  = reinterpret_cast<__half*>(sm + DOTW + YTOT);  // 2*XW halves

    const int tid  = threadIdx.x;
    const int lane = tid & 31;
    const int wid  = tid >> 5;
    const int b    = blockIdx.x;
    const int wbr  = wid >> 3;                  // warp's branch (0/1)
    const int wb   = (wid & 7) * 64;            // warp's channel base

    // ---- recurrence constants for channel h = tid ----
    const int h = tid;
    const float b1v = sigf(tau_n1[h]), b2v = sigf(tau_n2[h]), av = sigf(tau_m[h]);
    const u64 Bp  = pkf(b1v, b2v);
    const u64 Gp  = pkf(1.f - b1v, 1.f - b2v);
    const u64 GBp = pkf((1.f - b1v) * b1[h], (1.f - b2v) * b2[h]);
    const float amg = 1.f - av;
    const float wo  = Wo[h];
    const float bov = bo[0];

    // ---- W fragments (col-spec B frags) permanent in registers ----
    u32 BF[8][2][2];
    {
        const float* Ws = wbr ? W2 : W1;
        const int chl = lane >> 2;              // n within 8-tile
        const int kg  = 2 * (lane & 3);
#pragma unroll
        for (int nt = 0; nt < 8; nt++) {
            const int ch = wb + nt * 8 + chl;
#pragma unroll
            for (int kt = 0; kt < 2; kt++) {
                const int k0 = kt * 16 + kg;
                const float v0 = (k0     < KHALF) ? Ws[ch * KHALF + k0    ] : 0.f;
                const float v1 = (k0 + 1 < KHALF) ? Ws[ch * KHALF + k0 + 1] : 0.f;
                const float v2 = (k0 + 8 < KHALF) ? Ws[ch * KHALF + k0 + 8] : 0.f;
                const float v3 = (k0 + 9 < KHALF) ? Ws[ch * KHALF + k0 + 9] : 0.f;
                BF[nt][kt][0] = packh(v0, v1);
                BF[nt][kt][1] = packh(v2, v3);
            }
        }
    }

    // ---- x slot decomposition: 2 slots (of 1024) per thread ----
    const float* xg = x + (size_t)b * T_SZ * DIN;
    int xh_[2], gi_[2]; bool ok_[2];
#pragma unroll
    for (int i = 0; i < 2; i++) {
        const int sl = tid + i * 512;
        const int t  = sl >> 6, kk = sl & 63, br = kk >> 5, k = kk & 31;
        xh_[i] = t * 64 + kk;
        ok_[i] = (k < KHALF);
        gi_[i] = t * DIN + br * KHALF + k;
    }

    // prolog: stage 0 into xbuf0, prefetch stage 1
    float xv0 = ok_[0] ? xg[gi_[0]] : 0.f;
    float xv1 = ok_[1] ? xg[gi_[1]] : 0.f;
    xsm[xh_[0]] = __float2half_rn(xv0);
    xsm[xh_[1]] = __float2half_rn(xv1);
    xv0 = ok_[0] ? xg[640 + gi_[0]] : 0.f;
    xv1 = ok_[1] ? xg[640 + gi_[1]] : 0.f;
    __syncthreads();

    // lane constants for MMA dot store
    const int tlo  = lane >> 2;                 // t row (0..7) for c0/c1
    const int tc0  = tlo >> 2;                  // 0/1
    const int toff = tlo & 3;
    const int chl2 = 2 * (lane & 3);
    const u32 xbase = smem_u32(xsm);

    auto mma_stage = [&](int s) {
        const int buf = s & 1;
        u32 A[2][4];
#pragma unroll
        for (int kt = 0; kt < 2; kt++) {
            const u32 addr = xbase + (u32)buf * (XW * 2)
                           + (u32)(lane & 15) * 128
                           + (u32)(wbr * 32 + kt * 16 + ((lane >> 4) << 3)) * 2;
            ldmat4(A[kt], addr);
        }
        const int dB = wbr * BRW;
#pragma unroll
        for (int nt = 0; nt < 8; nt++) {
            float d0 = 0.f, d1 = 0.f, d2 = 0.f, d3 = 0.f;
            mma16816(d0, d1, d2, d3, A[0], BF[nt][0][0], BF[nt][0][1]);
            mma16816(d0, d1, d2, d3, A[1], BF[nt][1][0], BF[nt][1][1]);
            const int ch = wb + nt * 8 + chl2;
            const int w0 = dB + tc0 * TCW + ch * 4 + toff;
            dotsm[w0]               = d0;   // (t=tlo,   ch)
            dotsm[w0 + 4]           = d1;   // (t=tlo,   ch+1)
            dotsm[w0 + 2 * TCW]     = d2;   // (t=tlo+8, ch)
            dotsm[w0 + 2 * TCW + 4] = d3;   // (t=tlo+8, ch+1)
        }
    };

    auto ysum = [&](int s) {
        const float4* yr = reinterpret_cast<const float4*>(ysm + wid * YW);
        float acc = 0.f;
#pragma unroll
        for (int c = 0; c < 4; c++) {
            const float4 v = yr[lane + c * 32];
            acc += (v.x + v.y) + (v.z + v.w);
        }
#pragma unroll
        for (int off = 16; off; off >>= 1)
            acc += __shfl_xor_sync(0xFFFFFFFFu, acc, off);
        if (lane == 0)
            out[(size_t)b * T_SZ + s * ST + wid] =
                1.f / (1.f + __expf(-(acc + bov)));
    };

    u64 d12 = 0ull;
    float mem = 0.f;

    mma_stage(0);

    for (int s = 0; s < NSTAGES; s++) {
        __syncthreads();                        // dots(s) visible
        // stage x(s+1) from prefetch regs
        if (s + 1 < NSTAGES) {
            __half* xb = xsm + ((s + 1) & 1) * XW;
            xb[xh_[0]] = __float2half_rn(xv0);
            xb[xh_[1]] = __float2half_rn(xv1);
        }
        // recurrence over 16 timesteps, channel h
        {
            const int ch4 = h * 4;
#pragma unroll
            for (int tc = 0; tc < 4; tc++) {
                const float4 i1 = *reinterpret_cast<const float4*>(dotsm + tc * TCW + ch4);
                const float4 i2 = *reinterpret_cast<const float4*>(dotsm + BRW + tc * TCW + ch4);
                const float i1a[4] = {i1.x, i1.y, i1.z, i1.w};
                const float i2a[4] = {i2.x, i2.y, i2.z, i2.w};
#pragma unroll
                for (int j = 0; j < 4; j++) {
                    d12 = fma2(Bp, d12, fma2(Gp, pkf(i1a[j], i2a[j]), GBp));
                    const float2 dd = unpk(d12);
                    mem = __fmaf_rn(av, mem, amg * (dd.x + dd.y));
                    ysm[(tc * 4 + j) * YW + h] = wo * mem;
                }
            }
        }
        // prefetch x(s+2)
        if (s + 2 < NSTAGES) {
            xv0 = ok_[0] ? xg[(s + 2) * 640 + gi_[0]] : 0.f;
            xv1 = ok_[1] ? xg[(s + 2) * 640 + gi_[1]] : 0.f;
        }
        __syncthreads();                        // dots consumed; xbuf, ybuf ready
        if (s + 1 < NSTAGES) mma_stage(s + 1);
        ysum(s);
    }
}

}  // namespace

extern "C" void kernel_launch(void* const* d_in, const int* in_sizes, int n_in,
                              void* d_out, int out_size) {
    const float* x      = (const float*)d_in[0];
    const float* W1     = (const float*)d_in[1];
    const float* b1     = (const float*)d_in[2];
    const float* W2     = (const float*)d_in[3];
    const float* b2     = (const float*)d_in[4];
    const float* Wo     = (const float*)d_in[5];
    const float* bo     = (const float*)d_in[6];
    const float* tau_m  = (const float*)d_in[7];
    const float* tau_n1 = (const float*)d_in[8];
    const float* tau_n2 = (const float*)d_in[9];
    float* out = (float*)d_out;

    cudaFuncSetAttribute(sfnn_mma_kernel,
                         cudaFuncAttributeMaxDynamicSharedMemorySize, SMEM_BYTES);
    sfnn_mma_kernel<<<B_SZ, THREADS, SMEM_BYTES>>>(x, W1, b1, W2, b2, Wo, bo,
                                                   tau_m, tau_n1, tau_n2, out);
}

// round 7
// speedup vs baseline: 1.9010x; 1.0174x over previous
#include <cuda_runtime.h>
#include <cuda_fp16.h>
#include <cstdint>

// TwoBranchDH_SFNN, R6: merged-phase pipeline. One barrier per 16-timestep
// stage; dot slabs and y rows double-buffered so MMA(s+1), recurrence(s) and
// ysum(s-1) all overlap between the same pair of barriers.
// grid=128 (block per batch), 512 threads (16 warps), HMMA m16n8k16 fp16/f32.

namespace {

constexpr int B_SZ  = 128;
constexpr int T_SZ  = 2048;
constexpr int DIN   = 40;
constexpr int KHALF = 20;
constexpr int THREADS = 512;
constexpr int ST      = 16;             // timesteps per stage
constexpr int NSTAGES = T_SZ / ST;      // 128

// smem geometry (32-bit words)
constexpr int TCW  = 513 * 4;           // words per tc-slab (4 t x 512 ch padded)
constexpr int BRW  = 4 * TCW;           // per-branch dot words
constexpr int DOTW = 2 * BRW;           // both branches (one buffer)
constexpr int YW   = 520;               // y row stride (words)
constexpr int YTOT = 16 * YW;           // one y buffer
constexpr int XW   = 16 * 64;           // halves per x buffer
constexpr int SMEM_BYTES = (2 * DOTW + 2 * YTOT) * 4 + 2 * XW * 2;  // 201984 B

typedef unsigned long long u64;
typedef uint32_t u32;

__device__ __forceinline__ u32 smem_u32(const void* p) {
    u32 a;
    asm("{ .reg .u64 t; cvta.to.shared.u64 t, %1; cvt.u32.u64 %0, t; }"
        : "=r"(a) : "l"(p));
    return a;
}
__device__ __forceinline__ u64 pkf(float lo, float hi) {
    u64 r; asm("mov.b64 %0, {%1, %2};" : "=l"(r) : "f"(lo), "f"(hi)); return r;
}
__device__ __forceinline__ float2 unpk(u64 v) {
    float2 r; asm("mov.b64 {%0, %1}, %2;" : "=f"(r.x), "=f"(r.y) : "l"(v)); return r;
}
__device__ __forceinline__ u64 fma2(u64 a, u64 b, u64 c) {
    u64 d; asm("fma.rn.f32x2 %0, %1, %2, %3;" : "=l"(d) : "l"(a), "l"(b), "l"(c)); return d;
}

__device__ __forceinline__ void ldmat4(u32* r, u32 addr) {
    asm volatile("ldmatrix.sync.aligned.m8n8.x4.shared.b16 {%0,%1,%2,%3}, [%4];"
                 : "=r"(r[0]), "=r"(r[1]), "=r"(r[2]), "=r"(r[3]) : "r"(addr));
}
__device__ __forceinline__ void mma16816(float& d0, float& d1, float& d2, float& d3,
                                         const u32* a, u32 b0, u32 b1) {
    asm volatile("mma.sync.aligned.m16n8k16.row.col.f32.f16.f16.f32 "
                 "{%0,%1,%2,%3}, {%4,%5,%6,%7}, {%8,%9}, {%0,%1,%2,%3};"
                 : "+f"(d0), "+f"(d1), "+f"(d2), "+f"(d3)
                 : "r"(a[0]), "r"(a[1]), "r"(a[2]), "r"(a[3]), "r"(b0), "r"(b1));
}
__device__ __forceinline__ float sigf(float v) { return 1.0f / (1.0f + expf(-v)); }
__device__ __forceinline__ u32 packh(float a, float b) {
    __half2 h = __floats2half2_rn(a, b);
    return *reinterpret_cast<u32*>(&h);
}

__global__ void __launch_bounds__(THREADS, 1)
sfnn_mma_kernel(const float* __restrict__ x,
                const float* __restrict__ W1, const float* __restrict__ b1,
                const float* __restrict__ W2, const float* __restrict__ b2,
                const float* __restrict__ Wo, const float* __restrict__ bo,
                const float* __restrict__ tau_m, const float* __restrict__ tau_n1,
                const float* __restrict__ tau_n2, float* __restrict__ out) {
    extern __shared__ __align__(16) float sm[];
    float* dotsm = sm;                                   // 2*DOTW words
    float* ysm   = sm + 2 * DOTW;                        // 2*YTOT words
    __half* xsm  = reinterpret_cast<__half*>(sm + 2 * DOTW + 2 * YTOT);

    const int tid  = threadIdx.x;
    const int lane = tid & 31;
    const int wid  = tid >> 5;
    const int b    = blockIdx.x;
    const int wbr  = wid >> 3;                  // warp's branch (0/1)
    const int wb   = (wid & 7) * 64;            // warp's channel base

    // ---- recurrence constants for channel h = tid ----
    const int h = tid;
    const float b1v = sigf(tau_n1[h]), b2v = sigf(tau_n2[h]), av = sigf(tau_m[h]);
    const u64 Bp  = pkf(b1v, b2v);
    const u64 Gp  = pkf(1.f - b1v, 1.f - b2v);
    const u64 GBp = pkf((1.f - b1v) * b1[h], (1.f - b2v) * b2[h]);
    const float amg = 1.f - av;
    const float wo  = Wo[h];
    const float bov = bo[0];

    // ---- W fragments permanent in registers ----
    u32 BF[8][2][2];
    {
        const float* Ws = wbr ? W2 : W1;
        const int chl = lane >> 2;
        const int kg  = 2 * (lane & 3);
#pragma unroll
        for (int nt = 0; nt < 8; nt++) {
            const int ch = wb + nt * 8 + chl;
#pragma unroll
            for (int kt = 0; kt < 2; kt++) {
                const int k0 = kt * 16 + kg;
                const float v0 = (k0     < KHALF) ? Ws[ch * KHALF + k0    ] : 0.f;
                const float v1 = (k0 + 1 < KHALF) ? Ws[ch * KHALF + k0 + 1] : 0.f;
                const float v2 = (k0 + 8 < KHALF) ? Ws[ch * KHALF + k0 + 8] : 0.f;
                const float v3 = (k0 + 9 < KHALF) ? Ws[ch * KHALF + k0 + 9] : 0.f;
                BF[nt][kt][0] = packh(v0, v1);
                BF[nt][kt][1] = packh(v2, v3);
            }
        }
    }

    // ---- x slot decomposition: 2 slots (of 1024) per thread per stage ----
    const float* xg = x + (size_t)b * T_SZ * DIN;
    int xh_[2], gi_[2]; bool ok_[2];
#pragma unroll
    for (int i = 0; i < 2; i++) {
        const int sl = tid + i * 512;
        const int t  = sl >> 6, kk = sl & 63, br = kk >> 5, k = kk & 31;
        xh_[i] = t * 64 + kk;
        ok_[i] = (k < KHALF);
        gi_[i] = t * DIN + br * KHALF + k;
    }

    // lane constants for MMA dot store
    const int tlo  = lane >> 2;
    const int tc0  = tlo >> 2;
    const int toff = tlo & 3;
    const int chl2 = 2 * (lane & 3);
    const u32 xbase = smem_u32(xsm);

    auto mma_stage = [&](int s) {
        const int buf = s & 1;
        u32 A[2][4];
#pragma unroll
        for (int kt = 0; kt < 2; kt++) {
            const u32 addr = xbase + (u32)buf * (XW * 2)
                           + (u32)(lane & 15) * 128
                           + (u32)(wbr * 32 + kt * 16 + ((lane >> 4) << 3)) * 2;
            ldmat4(A[kt], addr);
        }
        const int dB = buf * DOTW + wbr * BRW;
#pragma unroll
        for (int nt = 0; nt < 8; nt++) {
            float d0 = 0.f, d1 = 0.f, d2 = 0.f, d3 = 0.f;
            mma16816(d0, d1, d2, d3, A[0], BF[nt][0][0], BF[nt][0][1]);
            mma16816(d0, d1, d2, d3, A[1], BF[nt][1][0], BF[nt][1][1]);
            const int ch = wb + nt * 8 + chl2;
            const int w0 = dB + tc0 * TCW + ch * 4 + toff;
            dotsm[w0]               = d0;   // (t=tlo,   ch)
            dotsm[w0 + 4]           = d1;   // (t=tlo,   ch+1)
            dotsm[w0 + 2 * TCW]     = d2;   // (t=tlo+8, ch)
            dotsm[w0 + 2 * TCW + 4] = d3;   // (t=tlo+8, ch+1)
        }
    };

    auto ysum = [&](int s) {
        const float4* yr = reinterpret_cast<const float4*>(
            ysm + (s & 1) * YTOT + wid * YW);
        float acc = 0.f;
#pragma unroll
        for (int c = 0; c < 4; c++) {
            const float4 v = yr[lane + c * 32];
            acc += (v.x + v.y) + (v.z + v.w);
        }
#pragma unroll
        for (int off = 16; off; off >>= 1)
            acc += __shfl_xor_sync(0xFFFFFFFFu, acc, off);
        if (lane == 0)
            out[(size_t)b * T_SZ + s * ST + wid] =
                1.f / (1.f + __expf(-(acc + bov)));
    };

    u64 d12 = 0ull;
    float mem = 0.f;

    // ---- prolog: stage x(0), x(1); prefetch x(2); first MMA ----
    {
        float v0 = ok_[0] ? xg[gi_[0]] : 0.f;
        float v1 = ok_[1] ? xg[gi_[1]] : 0.f;
        xsm[xh_[0]] = __float2half_rn(v0);
        xsm[xh_[1]] = __float2half_rn(v1);
        v0 = ok_[0] ? xg[640 + gi_[0]] : 0.f;
        v1 = ok_[1] ? xg[640 + gi_[1]] : 0.f;
        xsm[XW + xh_[0]] = __float2half_rn(v0);
        xsm[XW + xh_[1]] = __float2half_rn(v1);
    }
    float xv0 = ok_[0] ? xg[2 * 640 + gi_[0]] : 0.f;
    float xv1 = ok_[1] ? xg[2 * 640 + gi_[1]] : 0.f;
    __syncthreads();
    mma_stage(0);

    // ---- main loop: ONE barrier per stage, all phases overlapped ----
    for (int s = 0; s < NSTAGES; s++) {
        __syncthreads();   // dots(s), y(s-1), xbuf(s+1) visible

        if (s > 0) ysum(s - 1);
        if (s + 1 < NSTAGES) mma_stage(s + 1);

        // recurrence(s): reads dot buffer s&1, writes y buffer s&1
        {
            const int dB = (s & 1) * DOTW;
            float* yb = ysm + (s & 1) * YTOT;
            const int ch4 = h * 4;
#pragma unroll
            for (int tc = 0; tc < 4; tc++) {
                const float4 i1 = *reinterpret_cast<const float4*>(
                    dotsm + dB + tc * TCW + ch4);
                const float4 i2 = *reinterpret_cast<const float4*>(
                    dotsm + dB + BRW + tc * TCW + ch4);
                const float i1a[4] = {i1.x, i1.y, i1.z, i1.w};
                const float i2a[4] = {i2.x, i2.y, i2.z, i2.w};
#pragma unroll
                for (int j = 0; j < 4; j++) {
                    d12 = fma2(Bp, d12, fma2(Gp, pkf(i1a[j], i2a[j]), GBp));
                    const float2 dd = unpk(d12);
                    mem = __fmaf_rn(av, mem, amg * (dd.x + dd.y));
                    yb[(tc * 4 + j) * YW + h] = wo * mem;
                }
            }
        }

        // stage x(s+2) from prefetch regs; prefetch x(s+3)
        if (s + 2 < NSTAGES) {
            __half* xb = xsm + (s & 1) * XW;   // (s+2)&1 == s&1
            xb[xh_[0]] = __float2half_rn(xv0);
            xb[xh_[1]] = __float2half_rn(xv1);
            if (s + 3 < NSTAGES) {
                xv0 = ok_[0] ? xg[(s + 3) * 640 + gi_[0]] : 0.f;
                xv1 = ok_[1] ? xg[(s + 3) * 640 + gi_[1]] : 0.f;
            }
        }
    }

    __syncthreads();
    ysum(NSTAGES - 1);
}

}  // namespace

extern "C" void kernel_launch(void* const* d_in, const int* in_sizes, int n_in,
                              void* d_out, int out_size) {
    const float* x      = (const float*)d_in[0];
    const float* W1     = (const float*)d_in[1];
    const float* b1     = (const float*)d_in[2];
    const float* W2     = (const float*)d_in[3];
    const float* b2     = (const float*)d_in[4];
    const float* Wo     = (const float*)d_in[5];
    const float* bo     = (const float*)d_in[6];
    const float* tau_m  = (const float*)d_in[7];
    const float* tau_n1 = (const float*)d_in[8];
    const float* tau_n2 = (const float*)d_in[9];
    float* out = (float*)d_out;

    cudaFuncSetAttribute(sfnn_mma_kernel,
                         cudaFuncAttributeMaxDynamicSharedMemorySize, SMEM_BYTES);
    sfnn_mma_kernel<<<B_SZ, THREADS, SMEM_BYTES>>>(x, W1, b1, W2, b2, Wo, bo,
                                                   tau_m, tau_n1, tau_n2, out);
}